// round 2
// baseline (speedup 1.0000x reference)
#include <cuda_runtime.h>
#include <math.h>

// Problem constants (fixed by the reference setup_inputs)
#define B   4
#define C   64
#define Kc  19
#define HW  262144          // 512*512
#define EPSF 1e-7f

#define CHUNK       2048    // pixels per block for stats/apply kernels
#define CHUNKS      (HW / CHUNK)          // 128
#define THREADS     256
#define PIX_PER_T   (CHUNK / THREADS)     // 8 pixels -> 2 float4 groups
#define CT          8                     // channel tile for stats

// -------- device scratch (no allocations allowed) --------
__device__ float g_sum[B * Kc * C];
__device__ float g_sq [B * Kc * C];
__device__ int   g_cnt[B * Kc];
__device__ float g_scale[B * Kc * C];
__device__ float g_shift[B * Kc * C];

// -------- K0: zero the accumulators (must run every launch: graph replays) ----
__global__ void k_zero() {
    int tid = blockIdx.x * blockDim.x + threadIdx.x;
    int n = B * Kc * C;
    for (int i = tid; i < n; i += gridDim.x * blockDim.x) {
        g_sum[i] = 0.f;
        g_sq[i]  = 0.f;
    }
    if (tid < B * Kc) g_cnt[tid] = 0;
}

// -------- K1: per-(b,k,c) sum, sumsq, and per-(b,k) counts ----
__global__ __launch_bounds__(THREADS) void k_stats(const float* __restrict__ x,
                                                   const int* __restrict__ gt) {
    const int b       = blockIdx.x / CHUNKS;
    const int chunkId = blockIdx.x % CHUNKS;
    const int tid     = threadIdx.x;

    __shared__ float s_sum[CT][Kc + 1];
    __shared__ float s_sq [CT][Kc + 1];
    __shared__ int   s_cnt[Kc];

    // load this thread's 8 labels (2 x int4) into registers
    const int4* gt4 = (const int4*)(gt + (size_t)b * HW + (size_t)chunkId * CHUNK);
    int4 g0 = gt4[tid];
    int4 g1 = gt4[THREADS + tid];

    // ---- counts (once per pixel) ----
    if (tid < Kc) s_cnt[tid] = 0;
    __syncthreads();
    atomicAdd(&s_cnt[g0.x], 1); atomicAdd(&s_cnt[g0.y], 1);
    atomicAdd(&s_cnt[g0.z], 1); atomicAdd(&s_cnt[g0.w], 1);
    atomicAdd(&s_cnt[g1.x], 1); atomicAdd(&s_cnt[g1.y], 1);
    atomicAdd(&s_cnt[g1.z], 1); atomicAdd(&s_cnt[g1.w], 1);
    __syncthreads();
    if (tid < Kc) atomicAdd(&g_cnt[b * Kc + tid], s_cnt[tid]);

    // ---- channel-tiled sum / sumsq accumulation ----
    for (int ct = 0; ct < C / CT; ct++) {
        __syncthreads();
        for (int i = tid; i < CT * (Kc + 1); i += THREADS) {
            ((float*)s_sum)[i] = 0.f;
            ((float*)s_sq )[i] = 0.f;
        }
        __syncthreads();

        #pragma unroll
        for (int cc = 0; cc < CT; cc++) {
            const int c = ct * CT + cc;
            const float4* xp = (const float4*)(x + ((size_t)(b * C + c)) * HW
                                                 + (size_t)chunkId * CHUNK);
            #pragma unroll
            for (int j = 0; j < 2; j++) {
                float4 v = xp[j * THREADS + tid];
                int4 g = j ? g1 : g0;
                atomicAdd(&s_sum[cc][g.x], v.x); atomicAdd(&s_sq[cc][g.x], v.x * v.x);
                atomicAdd(&s_sum[cc][g.y], v.y); atomicAdd(&s_sq[cc][g.y], v.y * v.y);
                atomicAdd(&s_sum[cc][g.z], v.z); atomicAdd(&s_sq[cc][g.z], v.z * v.z);
                atomicAdd(&s_sum[cc][g.w], v.w); atomicAdd(&s_sq[cc][g.w], v.w * v.w);
            }
        }
        __syncthreads();

        for (int i = tid; i < CT * Kc; i += THREADS) {
            int cc = i / Kc, k = i % Kc;
            int c = ct * CT + cc;
            int gidx = (b * Kc + k) * C + c;
            atomicAdd(&g_sum[gidx], s_sum[cc][k]);
            atomicAdd(&g_sq [gidx], s_sq [cc][k]);
        }
    }
}

// -------- K2: finalize stats + tiny mixing einsum -> scale/shift tables ----
__global__ void k_finalize(const float* __restrict__ aug) {
    const int b = blockIdx.x;
    const int tid = threadIdx.x;

    __shared__ float s_mean[Kc * C];
    __shared__ float s_std [Kc * C];
    __shared__ float s_w   [Kc * Kc];
    __shared__ float s_wsum[Kc];
    __shared__ float s_cntf[Kc];

    if (tid < Kc) s_cntf[tid] = (float)g_cnt[b * Kc + tid];
    __syncthreads();

    // masked mixing weights
    for (int i = tid; i < Kc * Kc; i += blockDim.x) {
        int k = i % Kc;
        float v = aug[b * Kc * Kc + i];
        s_w[i] = (s_cntf[k] > 0.f) ? v : 0.f;
    }
    // mean / std
    for (int i = tid; i < Kc * C; i += blockDim.x) {
        int k = i / C;
        float cs = (s_cntf[k] > 0.f) ? s_cntf[k] : 1.f;
        float m = g_sum[b * Kc * C + i] / cs;
        float var = g_sq[b * Kc * C + i] / cs - m * m;
        var = fmaxf(var, 0.f);
        s_mean[i] = m;
        s_std[i]  = sqrtf(var) + EPSF;
    }
    __syncthreads();

    if (tid < Kc) {
        float s = 0.f;
        #pragma unroll
        for (int k = 0; k < Kc; k++) s += s_w[tid * Kc + k];
        s_wsum[tid] = fmaxf(s, EPSF);
    }
    __syncthreads();

    // mix + fold into per-(target class, channel) affine
    for (int idx = tid; idx < Kc * C; idx += blockDim.x) {
        int i = idx / C;
        float inv = 1.f / s_wsum[i];
        int c = idx % C;
        float mm = 0.f, ms = 0.f;
        #pragma unroll
        for (int k = 0; k < Kc; k++) {
            float wn = s_w[i * Kc + k] * inv;
            mm += wn * s_mean[k * C + c];
            ms += wn * s_std [k * C + c];
        }
        float sc = ms / s_std[idx];
        g_scale[b * Kc * C + idx] = sc;
        g_shift[b * Kc * C + idx] = mm - s_mean[idx] * sc;
    }
}

// -------- K3: apply out = x * scale[g] + shift[g] ----
__global__ __launch_bounds__(THREADS) void k_apply(const float* __restrict__ x,
                                                   const int* __restrict__ gt,
                                                   float* __restrict__ out) {
    const int b       = blockIdx.x / CHUNKS;
    const int chunkId = blockIdx.x % CHUNKS;
    const int tid     = threadIdx.x;

    // transposed layout [c][k] with pad: lanes share c, k varies -> conflict-free
    __shared__ float s_scale[C][Kc + 1];
    __shared__ float s_shift[C][Kc + 1];

    for (int i = tid; i < Kc * C; i += THREADS) {
        int k = i / C, c = i % C;
        s_scale[c][k] = g_scale[b * Kc * C + i];
        s_shift[c][k] = g_shift[b * Kc * C + i];
    }

    const int4* gt4 = (const int4*)(gt + (size_t)b * HW + (size_t)chunkId * CHUNK);
    int4 g0 = gt4[tid];
    int4 g1 = gt4[THREADS + tid];
    __syncthreads();

    #pragma unroll 4
    for (int c = 0; c < C; c++) {
        const size_t base = ((size_t)(b * C + c)) * HW + (size_t)chunkId * CHUNK;
        const float4* xp = (const float4*)(x + base);
        float4* op = (float4*)(out + base);
        #pragma unroll
        for (int j = 0; j < 2; j++) {
            float4 v = xp[j * THREADS + tid];
            int4 g = j ? g1 : g0;
            float4 o;
            o.x = fmaf(v.x, s_scale[c][g.x], s_shift[c][g.x]);
            o.y = fmaf(v.y, s_scale[c][g.y], s_shift[c][g.y]);
            o.z = fmaf(v.z, s_scale[c][g.z], s_shift[c][g.z]);
            o.w = fmaf(v.w, s_scale[c][g.w], s_shift[c][g.w]);
            op[j * THREADS + tid] = o;
        }
    }
}

extern "C" void kernel_launch(void* const* d_in, const int* in_sizes, int n_in,
                              void* d_out, int out_size) {
    const float* x   = (const float*)d_in[0];
    const int*   gt  = (const int*)d_in[1];
    const float* aug = (const float*)d_in[2];
    float* out = (float*)d_out;

    k_zero<<<10, 1024>>>();
    k_stats<<<B * CHUNKS, THREADS>>>(x, gt);
    k_finalize<<<B, 256>>>(aug);
    k_apply<<<B * CHUNKS, THREADS>>>(x, gt, out);
}

// round 5
// speedup vs baseline: 3.1188x; 3.1188x over previous
#include <cuda_runtime.h>
#include <math.h>

// Problem constants (fixed by the reference setup_inputs)
#define B    4
#define C    64
#define Kc   19
#define HW   262144          // 512*512
#define EPSF 1e-7f

#define THREADS  256

// ---- stats kernel tiling ----
#define CHUNK_S  8192                   // pixels per stats block
#define SCHUNKS  (HW / CHUNK_S)         // 32
#define CG       8                      // channels per stats block
#define NCG      (C / CG)               // 8
#define SITERS   (CHUNK_S / (THREADS*4))// 8 float4 per thread

// ---- apply kernel tiling ----
#define CHUNK_A  1024                   // pixels per apply block
#define ACHUNKS  (HW / CHUNK_A)         // 256

// -------- device scratch (no allocations allowed) --------
__device__ float2 g_acc[B * Kc * C];     // (sum, sumsq) per (b,k,c)
__device__ int    g_cnt[B * Kc];
__device__ float2 g_tab[B * C * Kc];     // (scale, shift) per (b,c,k)

// -------- K0: zero accumulators (graph replays -> must run every launch) ----
__global__ void k_zero() {
    int tid = blockIdx.x * blockDim.x + threadIdx.x;
    int n = B * Kc * C;
    for (int i = tid; i < n; i += gridDim.x * blockDim.x)
        g_acc[i] = make_float2(0.f, 0.f);
    if (tid < B * Kc) g_cnt[tid] = 0;
}

// -------- K1: per-(b,k) pixel counts (labels only: 4 MB read) ----
__global__ __launch_bounds__(THREADS) void k_count(const int* __restrict__ gt) {
    __shared__ int s_cnt[Kc];
    const int tid = threadIdx.x;
    if (tid < Kc) s_cnt[tid] = 0;
    __syncthreads();

    const int per_block = (B * HW) / gridDim.x;       // 2048 for grid=512
    const int base = blockIdx.x * per_block;
    const int b = base / HW;                           // chunk lies within one image
    const int4* g4 = (const int4*)(gt + base);
    for (int i = tid; i < per_block / 4; i += THREADS) {
        int4 g = g4[i];
        atomicAdd(&s_cnt[g.x], 1); atomicAdd(&s_cnt[g.y], 1);
        atomicAdd(&s_cnt[g.z], 1); atomicAdd(&s_cnt[g.w], 1);
    }
    __syncthreads();
    if (tid < Kc && s_cnt[tid] > 0) atomicAdd(&g_cnt[b * Kc + tid], s_cnt[tid]);
}

// -------- K2: atomic-free stats: thread-private shared slabs ----
// block = (b, pixel chunk, channel group); grid = B*SCHUNKS*NCG = 1024
__global__ __launch_bounds__(THREADS) void k_stats(const float* __restrict__ x,
                                                   const int* __restrict__ gt) {
    __shared__ unsigned char s_lbl[CHUNK_S];               // 8 KB
    __shared__ float2 s_acc[Kc][THREADS];                  // 38.9 KB

    const int bid   = blockIdx.x;
    const int cg    = bid % NCG;
    const int chunk = (bid / NCG) % SCHUNKS;
    const int b     = bid / (NCG * SCHUNKS);
    const int tid   = threadIdx.x;
    const int lane  = tid & 31;
    const int wid   = tid >> 5;

    // pack labels to uint8 in shared (once per block, reused for CG channels)
    {
        const int4* gt4 = (const int4*)(gt + (size_t)b * HW + (size_t)chunk * CHUNK_S);
        uchar4* l4 = (uchar4*)s_lbl;
        #pragma unroll
        for (int i = 0; i < CHUNK_S / (THREADS * 4); i++) {    // 8
            int4 g = gt4[i * THREADS + tid];
            l4[i * THREADS + tid] = make_uchar4((unsigned char)g.x, (unsigned char)g.y,
                                                (unsigned char)g.z, (unsigned char)g.w);
        }
    }

    for (int cc = 0; cc < CG; cc++) {
        const int c = cg * CG + cc;
        __syncthreads();
        #pragma unroll
        for (int k = 0; k < Kc; k++) s_acc[k][tid] = make_float2(0.f, 0.f);
        __syncthreads();

        const float4* xp = (const float4*)(x + ((size_t)(b * C + c)) * HW
                                             + (size_t)chunk * CHUNK_S);
        const uchar4* l4 = (const uchar4*)s_lbl;
        #pragma unroll
        for (int i = 0; i < SITERS; i++) {
            float4 v = xp[i * THREADS + tid];
            uchar4 g = l4[i * THREADS + tid];
            float2 a;
            a = s_acc[g.x][tid]; a.x += v.x; a.y = fmaf(v.x, v.x, a.y); s_acc[g.x][tid] = a;
            a = s_acc[g.y][tid]; a.x += v.y; a.y = fmaf(v.y, v.y, a.y); s_acc[g.y][tid] = a;
            a = s_acc[g.z][tid]; a.x += v.z; a.y = fmaf(v.z, v.z, a.y); s_acc[g.z][tid] = a;
            a = s_acc[g.w][tid]; a.x += v.w; a.y = fmaf(v.w, v.w, a.y); s_acc[g.w][tid] = a;
        }
        __syncthreads();

        // reduce 256 columns -> 1 per class; warp w handles classes w, w+8, w+16
        for (int k = wid; k < Kc; k += 8) {
            float2 s = make_float2(0.f, 0.f);
            #pragma unroll
            for (int j = 0; j < THREADS / 32; j++) {
                float2 a = s_acc[k][lane + 32 * j];
                s.x += a.x; s.y += a.y;
            }
            #pragma unroll
            for (int d = 16; d > 0; d >>= 1) {
                s.x += __shfl_down_sync(0xffffffffu, s.x, d);
                s.y += __shfl_down_sync(0xffffffffu, s.y, d);
            }
            if (lane == 0) {
                float2* dst = &g_acc[(b * Kc + k) * C + c];
                atomicAdd(&dst->x, s.x);
                atomicAdd(&dst->y, s.y);
            }
        }
    }
}

// -------- K3: finalize stats + mixing einsum -> (scale,shift) table ----
__global__ void k_finalize(const float* __restrict__ aug) {
    const int b = blockIdx.x;
    const int tid = threadIdx.x;

    __shared__ float s_mean[Kc * C];
    __shared__ float s_std [Kc * C];
    __shared__ float s_w   [Kc * Kc];
    __shared__ float s_wsum[Kc];
    __shared__ float s_cntf[Kc];

    if (tid < Kc) s_cntf[tid] = (float)g_cnt[b * Kc + tid];
    __syncthreads();

    for (int i = tid; i < Kc * Kc; i += blockDim.x) {
        int k = i % Kc;
        float v = aug[b * Kc * Kc + i];
        s_w[i] = (s_cntf[k] > 0.f) ? v : 0.f;
    }
    for (int i = tid; i < Kc * C; i += blockDim.x) {        // i = k*C + c
        int k = i / C;
        float cs = (s_cntf[k] > 0.f) ? s_cntf[k] : 1.f;
        float2 a = g_acc[b * Kc * C + i];
        float m = a.x / cs;
        float var = fmaxf(a.y / cs - m * m, 0.f);
        s_mean[i] = m;
        s_std[i]  = sqrtf(var) + EPSF;
    }
    __syncthreads();

    if (tid < Kc) {
        float s = 0.f;
        #pragma unroll
        for (int k = 0; k < Kc; k++) s += s_w[tid * Kc + k];
        s_wsum[tid] = fmaxf(s, EPSF);
    }
    __syncthreads();

    for (int idx = tid; idx < Kc * C; idx += blockDim.x) {  // idx = i*C + c
        int i = idx / C;
        int c = idx % C;
        float inv = 1.f / s_wsum[i];
        float mm = 0.f, ms = 0.f;
        #pragma unroll
        for (int k = 0; k < Kc; k++) {
            float wn = s_w[i * Kc + k] * inv;
            mm += wn * s_mean[k * C + c];
            ms += wn * s_std [k * C + c];
        }
        float sc = ms / s_std[idx];
        g_tab[(b * C + c) * Kc + i] = make_float2(sc, mm - s_mean[idx] * sc);
    }
}

// -------- K4: apply out = x * scale[b,c,g] + shift[b,c,g] ----
// block = (b, pixel chunk of 1024); grid = B*ACHUNKS = 1024
__global__ __launch_bounds__(THREADS) void k_apply(const float* __restrict__ x,
                                                   const int* __restrict__ gt,
                                                   float* __restrict__ out) {
    __shared__ float2 s_tab[C][Kc + 1];                    // 10.2 KB

    const int chunk = blockIdx.x % ACHUNKS;
    const int b     = blockIdx.x / ACHUNKS;
    const int tid   = threadIdx.x;

    for (int i = tid; i < C * Kc; i += THREADS) {
        int c = i / Kc, k = i % Kc;
        s_tab[c][k] = g_tab[b * C * Kc + i];
    }
    const int4 g = ((const int4*)(gt + (size_t)b * HW + (size_t)chunk * CHUNK_A))[tid];
    __syncthreads();

    #pragma unroll 4
    for (int c = 0; c < C; c++) {
        const size_t base = ((size_t)(b * C + c)) * HW + (size_t)chunk * CHUNK_A;
        float4 v = ((const float4*)(x + base))[tid];
        float2 t0 = s_tab[c][g.x];
        float2 t1 = s_tab[c][g.y];
        float2 t2 = s_tab[c][g.z];
        float2 t3 = s_tab[c][g.w];
        float4 o;
        o.x = fmaf(v.x, t0.x, t0.y);
        o.y = fmaf(v.y, t1.x, t1.y);
        o.z = fmaf(v.z, t2.x, t2.y);
        o.w = fmaf(v.w, t3.x, t3.y);
        ((float4*)(out + base))[tid] = o;
    }
}

extern "C" void kernel_launch(void* const* d_in, const int* in_sizes, int n_in,
                              void* d_out, int out_size) {
    const float* x   = (const float*)d_in[0];
    const int*   gt  = (const int*)d_in[1];
    const float* aug = (const float*)d_in[2];
    float* out = (float*)d_out;

    k_zero<<<10, 1024>>>();
    k_count<<<512, THREADS>>>(gt);
    k_stats<<<B * SCHUNKS * NCG, THREADS>>>(x, gt);
    k_finalize<<<B, 256>>>(aug);
    k_apply<<<B * ACHUNKS, THREADS>>>(x, gt, out);
}

// round 7
// speedup vs baseline: 3.3296x; 1.0676x over previous
#include <cuda_runtime.h>
#include <math.h>

// Problem constants (fixed by the reference setup_inputs)
#define B    4
#define C    64
#define Kc   19
#define HW   262144          // 512*512
#define EPSF 1e-7f

#define THREADS  256

// ---- stats kernel tiling ----
#define CHUNK_S  8192                   // pixels per stats block
#define SCHUNKS  (HW / CHUNK_S)         // 32
#define CG       8                      // channels per stats block
#define NCG      (C / CG)               // 8
#define SITERS   (CHUNK_S / (THREADS*4))// 8 float4 per thread

// ---- apply kernel tiling ----
#define CHUNK_A  1024                   // pixels per apply block
#define ACHUNKS  (HW / CHUNK_A)         // 256
#define CGA      32                     // channels per apply block
#define NCGA     (C / CGA)              // 2

// ---- finalize tiling ----
#define FCQ      4                      // channel-quarters per image
#define FCW      (C / FCQ)              // 16 channels per finalize block

// -------- device scratch (no allocations allowed) --------
__device__ float2 g_acc[B * Kc * C];     // (sum, sumsq) per (b,k,c)
__device__ int    g_cnt[B * Kc];
__device__ float2 g_tab[B * C * Kc];     // (scale, shift) per (b,c,k)

// -------- K0: zero accumulators (graph replays -> must run every launch) ----
__global__ void k_zero() {
    int tid = blockIdx.x * blockDim.x + threadIdx.x;
    int n = B * Kc * C;
    for (int i = tid; i < n; i += gridDim.x * blockDim.x)
        g_acc[i] = make_float2(0.f, 0.f);
    if (tid < B * Kc) g_cnt[tid] = 0;
}

// -------- K1: atomic-free stats (thread-private shared slabs) + fused counts ----
// block = (b, pixel chunk, channel group); grid = B*SCHUNKS*NCG = 1024
__global__ __launch_bounds__(THREADS) void k_stats(const float* __restrict__ x,
                                                   const int* __restrict__ gt) {
    __shared__ unsigned char s_lbl[CHUNK_S];               // 8 KB
    __shared__ float2 s_acc[Kc][THREADS];                  // 38.9 KB
    __shared__ int s_cnt[Kc];

    const int bid   = blockIdx.x;
    const int cg    = bid % NCG;
    const int chunk = (bid / NCG) % SCHUNKS;
    const int b     = bid / (NCG * SCHUNKS);
    const int tid   = threadIdx.x;
    const int lane  = tid & 31;
    const int wid   = tid >> 5;
    const bool docnt = (cg == 0);

    if (docnt && tid < Kc) s_cnt[tid] = 0;
    __syncthreads();

    // pack labels to uint8 in shared (once per block, reused for CG channels);
    // cg==0 blocks also count labels (shared atomics, light contention)
    {
        const int4* gt4 = (const int4*)(gt + (size_t)b * HW + (size_t)chunk * CHUNK_S);
        uchar4* l4 = (uchar4*)s_lbl;
        #pragma unroll
        for (int i = 0; i < CHUNK_S / (THREADS * 4); i++) {    // 8
            int4 g = gt4[i * THREADS + tid];
            l4[i * THREADS + tid] = make_uchar4((unsigned char)g.x, (unsigned char)g.y,
                                                (unsigned char)g.z, (unsigned char)g.w);
            if (docnt) {
                atomicAdd(&s_cnt[g.x], 1); atomicAdd(&s_cnt[g.y], 1);
                atomicAdd(&s_cnt[g.z], 1); atomicAdd(&s_cnt[g.w], 1);
            }
        }
    }
    __syncthreads();
    if (docnt && tid < Kc && s_cnt[tid] > 0)
        atomicAdd(&g_cnt[b * Kc + tid], s_cnt[tid]);

    for (int cc = 0; cc < CG; cc++) {
        const int c = cg * CG + cc;
        __syncthreads();
        #pragma unroll
        for (int k = 0; k < Kc; k++) s_acc[k][tid] = make_float2(0.f, 0.f);
        __syncthreads();

        const float4* xp = (const float4*)(x + ((size_t)(b * C + c)) * HW
                                             + (size_t)chunk * CHUNK_S);
        const uchar4* l4 = (const uchar4*)s_lbl;
        #pragma unroll
        for (int i = 0; i < SITERS; i++) {
            float4 v = xp[i * THREADS + tid];
            uchar4 g = l4[i * THREADS + tid];
            float2 a;
            a = s_acc[g.x][tid]; a.x += v.x; a.y = fmaf(v.x, v.x, a.y); s_acc[g.x][tid] = a;
            a = s_acc[g.y][tid]; a.x += v.y; a.y = fmaf(v.y, v.y, a.y); s_acc[g.y][tid] = a;
            a = s_acc[g.z][tid]; a.x += v.z; a.y = fmaf(v.z, v.z, a.y); s_acc[g.z][tid] = a;
            a = s_acc[g.w][tid]; a.x += v.w; a.y = fmaf(v.w, v.w, a.y); s_acc[g.w][tid] = a;
        }
        __syncthreads();

        // reduce 256 columns -> 1 per class; warp w handles classes w, w+8, w+16
        for (int k = wid; k < Kc; k += 8) {
            float2 s = make_float2(0.f, 0.f);
            #pragma unroll
            for (int j = 0; j < THREADS / 32; j++) {
                float2 a = s_acc[k][lane + 32 * j];
                s.x += a.x; s.y += a.y;
            }
            #pragma unroll
            for (int d = 16; d > 0; d >>= 1) {
                s.x += __shfl_down_sync(0xffffffffu, s.x, d);
                s.y += __shfl_down_sync(0xffffffffu, s.y, d);
            }
            if (lane == 0) {
                float2* dst = &g_acc[(b * Kc + k) * C + c];
                atomicAdd(&dst->x, s.x);
                atomicAdd(&dst->y, s.y);
            }
        }
    }
}

// -------- K2: finalize stats + mixing einsum -> (scale,shift) table ----
// grid = B*FCQ = 16; block owns channels [cq*16, cq*16+16) of image b
__global__ __launch_bounds__(256) void k_finalize(const float* __restrict__ aug) {
    const int b  = blockIdx.x / FCQ;
    const int c0 = (blockIdx.x % FCQ) * FCW;
    const int tid = threadIdx.x;

    __shared__ float s_mean[Kc * FCW];
    __shared__ float s_std [Kc * FCW];
    __shared__ float s_w   [Kc * Kc];
    __shared__ float s_wsum[Kc];
    __shared__ float s_cntf[Kc];

    if (tid < Kc) s_cntf[tid] = (float)g_cnt[b * Kc + tid];
    __syncthreads();

    for (int i = tid; i < Kc * Kc; i += blockDim.x) {
        int k = i % Kc;
        float v = aug[b * Kc * Kc + i];
        s_w[i] = (s_cntf[k] > 0.f) ? v : 0.f;
    }
    for (int i = tid; i < Kc * FCW; i += blockDim.x) {      // i = k*FCW + cl
        int k = i / FCW, cl = i % FCW;
        float cs = (s_cntf[k] > 0.f) ? s_cntf[k] : 1.f;
        float2 a = g_acc[(b * Kc + k) * C + c0 + cl];
        float m = a.x / cs;
        float var = fmaxf(a.y / cs - m * m, 0.f);
        s_mean[i] = m;
        s_std[i]  = sqrtf(var) + EPSF;
    }
    __syncthreads();

    if (tid < Kc) {
        float s = 0.f;
        #pragma unroll
        for (int k = 0; k < Kc; k++) s += s_w[tid * Kc + k];
        s_wsum[tid] = fmaxf(s, EPSF);
    }
    __syncthreads();

    for (int idx = tid; idx < Kc * FCW; idx += blockDim.x) { // idx = i*FCW + cl
        int i = idx / FCW;
        int cl = idx % FCW;
        float inv = 1.f / s_wsum[i];
        float mm = 0.f, ms = 0.f;
        #pragma unroll
        for (int k = 0; k < Kc; k++) {
            float wn = s_w[i * Kc + k] * inv;
            mm += wn * s_mean[k * FCW + cl];
            ms += wn * s_std [k * FCW + cl];
        }
        float sc = ms / s_std[idx];
        g_tab[(b * C + c0 + cl) * Kc + i] = make_float2(sc, mm - s_mean[idx] * sc);
    }
}

// -------- K3: apply out = x * scale[b,c,g] + shift[b,c,g] ----
// block = (b, pixel chunk of 1024, channel half); grid = B*ACHUNKS*NCGA = 2048
__global__ __launch_bounds__(THREADS) void k_apply(const float* __restrict__ x,
                                                   const int* __restrict__ gt,
                                                   float* __restrict__ out) {
    __shared__ float2 s_tab[CGA][Kc + 1];                  // 5.1 KB

    const int bid   = blockIdx.x;
    const int cga   = bid % NCGA;
    const int chunk = (bid / NCGA) % ACHUNKS;
    const int b     = bid / (NCGA * ACHUNKS);
    const int tid   = threadIdx.x;
    const int cbase = cga * CGA;

    for (int i = tid; i < CGA * Kc; i += THREADS) {
        int c = i / Kc, k = i % Kc;
        s_tab[c][k] = g_tab[(b * C + cbase + c) * Kc + k];
    }
    const int4 g = ((const int4*)(gt + (size_t)b * HW + (size_t)chunk * CHUNK_A))[tid];
    __syncthreads();

    #pragma unroll 4
    for (int c = 0; c < CGA; c++) {
        const size_t base = ((size_t)(b * C + cbase + c)) * HW + (size_t)chunk * CHUNK_A;
        float4 v = ((const float4*)(x + base))[tid];
        float2 t0 = s_tab[c][g.x];
        float2 t1 = s_tab[c][g.y];
        float2 t2 = s_tab[c][g.z];
        float2 t3 = s_tab[c][g.w];
        float4 o;
        o.x = fmaf(v.x, t0.x, t0.y);
        o.y = fmaf(v.y, t1.x, t1.y);
        o.z = fmaf(v.z, t2.x, t2.y);
        o.w = fmaf(v.w, t3.x, t3.y);
        ((float4*)(out + base))[tid] = o;
    }
}

extern "C" void kernel_launch(void* const* d_in, const int* in_sizes, int n_in,
                              void* d_out, int out_size) {
    const float* x   = (const float*)d_in[0];
    const int*   gt  = (const int*)d_in[1];
    const float* aug = (const float*)d_in[2];
    float* out = (float*)d_out;

    k_zero<<<10, 1024>>>();
    k_stats<<<B * SCHUNKS * NCG, THREADS>>>(x, gt);
    k_finalize<<<B * FCQ, 256>>>(aug);
    k_apply<<<B * ACHUNKS * NCGA, THREADS>>>(x, gt, out);
}